// round 17
// baseline (speedup 1.0000x reference)
#include <cuda_runtime.h>
#include <cuda_bf16.h>
#include <cstdint>

// ISTA deconvolution via mma.sync bf16 (round 17).
// = R14 wide-M math (verified, rel_err 5.6e-6) with both blockers fixed:
//   - g_resid stored ROW-MAJOR via SMEM transpose + coalesced float4 stores,
//     so mode1 stages B identically to mode0 (same [n][jj] layout, non-trans
//     ldsm, same 50KB footprint) -> SMEM 71.7KB -> 3 CTAs/SM for BOTH modes.
//   - __launch_bounds__(256,3) (84-reg cap) + A-lo ldsm deferred until after
//     the hh/hl combos -> peak live regs ~74, no spills.
// GEMM per CTA: 256 out cols x 32 batch rows; warp w owns 32 cols.
//   A[mi][kk] = w[kk-mi-1] (32x160 band Toeplitz, shared by all warps)
//   B[n][jj]  = src[r0+n][c0-64+jj], jj in [0,384); jj0 = 32w + 16s
//   D[mi,n]   = sum_d w[d]*src[r0+n][(c0+32w+mi)+d-63]   (TF SAME)
// mode0: w = delta63 - h, src=y,      dst=g_resid (residual, row-major)
// mode1: w = h reversed,  src=g_resid, dst=out with closed-form ISTA
//   x_T = T*sign(s*u)*max(|s*u|-lambda, 0).
// Split bf16 (hi+lo), combos hh+hl+lh, fp32 accumulate.

#define LDIM 4096
#define BDIM 4096
#define KW   128
#define LAMBDA 0.1f
#define TITER  5.0f
#define NTH  256
#define ROWS 32
#define COLS 256

#define AS   168                     // A stride bf16: 336B = 21*16 -> conflict-free
#define A_BYTES (32 * AS * 2)        // 10752
#define BS   392                     // B stride bf16: 784B = 49*16
#define B_BYTES (ROWS * BS * 2)      // 25088
#define SM_AHI 0
#define SM_ALO A_BYTES
#define SM_BHI (2 * A_BYTES)         // 21504
#define SM_BLO (SM_BHI + B_BYTES)    // 46592
#define SM_TOTAL (SM_BHI + 2 * B_BYTES)   // 71680 -> 3 CTAs/SM

__device__ float g_resid[(size_t)BDIM * LDIM];   // residual, ROW-MAJOR

__device__ __forceinline__ uint32_t smem_u32(const void* p) {
    uint32_t a;
    asm("{ .reg .u64 t; cvta.to.shared.u64 t, %1; cvt.u32.u64 %0, t; }"
        : "=r"(a) : "l"(p));
    return a;
}
__device__ __forceinline__ void ldsm_x4(uint32_t* r, uint32_t addr) {
    asm volatile("ldmatrix.sync.aligned.m8n8.x4.shared.b16 {%0,%1,%2,%3}, [%4];"
        : "=r"(r[0]), "=r"(r[1]), "=r"(r[2]), "=r"(r[3]) : "r"(addr));
}
__device__ __forceinline__ void mma_bf16(float* c, const uint32_t* a, const uint32_t* b) {
    asm volatile(
        "mma.sync.aligned.m16n8k16.row.col.f32.bf16.bf16.f32 "
        "{%0,%1,%2,%3}, {%4,%5,%6,%7}, {%8,%9}, {%0,%1,%2,%3};"
        : "+f"(c[0]), "+f"(c[1]), "+f"(c[2]), "+f"(c[3])
        : "r"(a[0]), "r"(a[1]), "r"(a[2]), "r"(a[3]), "r"(b[0]), "r"(b[1]));
}
__device__ __forceinline__ void split_bf16(float v, __nv_bfloat16& hi, __nv_bfloat16& lo) {
    hi = __float2bfloat16(v);
    lo = __float2bfloat16(v - __bfloat162float(hi));
}

template <int MODE>
__global__ __launch_bounds__(NTH, 3)
void conv_mma_kernel(const float* __restrict__ y,
                     const float* __restrict__ h,
                     const float* __restrict__ step,
                     float* __restrict__ out)
{
    extern __shared__ __align__(16) char smem[];
    const int tid = threadIdx.x, w = tid >> 5, lane = tid & 31;
    const int c0 = blockIdx.x * COLS;
    const int r0 = blockIdx.y * ROWS;
    const float* src = (MODE == 0) ? y : g_resid;
    __nv_bfloat16* Ahi = (__nv_bfloat16*)(smem + SM_AHI);
    __nv_bfloat16* Alo = (__nv_bfloat16*)(smem + SM_ALO);
    __nv_bfloat16* Bhi = (__nv_bfloat16*)(smem + SM_BHI);
    __nv_bfloat16* Blo = (__nv_bfloat16*)(smem + SM_BLO);

    // ---- Toeplitz A (32 x 160), split hi/lo ----
    for (int idx = tid; idx < 32 * 160; idx += NTH) {
        int mi = idx / 160, jj = idx - mi * 160;
        int d = jj - mi - 1;
        float wv = 0.0f;
        if (0 <= d && d < KW)
            wv = (MODE == 0) ? ((d == 63) ? 1.0f : 0.0f) - __ldg(h + d)
                             : __ldg(h + (KW - 1) - d);
        __nv_bfloat16 hi, lo;
        split_bf16(wv, hi, lo);
        Ahi[mi * AS + jj] = hi;
        Alo[mi * AS + jj] = lo;
    }

    // ---- Stage B[n][jj] = src[r0+n][c0-64+jj], split hi/lo ----
#pragma unroll
    for (int it = 0; it < 12; it++) {
        int idx = tid + it * NTH;                 // 32 rows x 96 float4
        int n = idx / 96, q = idx - n * 96;
        int gc = c0 - 64 + 4 * q;                 // 4-aligned
        const float* base = src + (size_t)(r0 + n) * LDIM;
        float4 f;
        if ((unsigned)gc <= (unsigned)(LDIM - 4)) {
            f = *(const float4*)(base + gc);
        } else {
            f.x = ((unsigned)(gc + 0) < LDIM) ? base[gc + 0] : 0.0f;
            f.y = ((unsigned)(gc + 1) < LDIM) ? base[gc + 1] : 0.0f;
            f.z = ((unsigned)(gc + 2) < LDIM) ? base[gc + 2] : 0.0f;
            f.w = ((unsigned)(gc + 3) < LDIM) ? base[gc + 3] : 0.0f;
        }
        __nv_bfloat16 h0, l0, h1, l1, h2, l2, h3, l3;
        split_bf16(f.x, h0, l0); split_bf16(f.y, h1, l1);
        split_bf16(f.z, h2, l2); split_bf16(f.w, h3, l3);
        __nv_bfloat162* dh = (__nv_bfloat162*)(Bhi + n * BS + 4 * q);
        __nv_bfloat162* dl = (__nv_bfloat162*)(Blo + n * BS + 4 * q);
        dh[0] = __halves2bfloat162(h0, h1); dh[1] = __halves2bfloat162(h2, h3);
        dl[0] = __halves2bfloat162(l0, l1); dl[1] = __halves2bfloat162(l2, l3);
    }
    __syncthreads();

    // ---- MMA mainloop: 10 ksteps; 8 LDSM -> 24 MMAs, A-lo loads deferred ----
    float acc[2][4][4];
#pragma unroll
    for (int m = 0; m < 2; m++)
#pragma unroll
        for (int i = 0; i < 4; i++)
#pragma unroll
            for (int j = 0; j < 4; j++) acc[m][i][j] = 0.0f;

    const uint32_t sb = smem_u32(smem);
    const uint32_t aCol = (lane & 16) ? 8u : 0u;
    const uint32_t aHi0 = sb + SM_AHI + ((((lane & 15) +  0) * AS + aCol) << 1);
    const uint32_t aHi1 = sb + SM_AHI + ((((lane & 15) + 16) * AS + aCol) << 1);
    const uint32_t b0n = (lane & 7) + ((lane & 16) ? 8 : 0);
    const uint32_t b0j = (lane & 8) ? 8 : 0;
    const uint32_t bA0 = sb + SM_BHI + (((0 + b0n) * BS + b0j) << 1);
    const uint32_t bA1 = sb + SM_BHI + (((16 + b0n) * BS + b0j) << 1);

#pragma unroll
    for (int s = 0; s < 10; s++) {
        uint32_t ah0[4], ah1[4], bh0[4], bh1[4], bl0[4], bl1[4];
        ldsm_x4(ah0, aHi0 + 32u * s);
        ldsm_x4(ah1, aHi1 + 32u * s);
        const uint32_t bo = (32u * w + 16u * s) << 1;
        ldsm_x4(bh0, bA0 + bo); ldsm_x4(bh1, bA1 + bo);
        ldsm_x4(bl0, bA0 + bo + B_BYTES); ldsm_x4(bl1, bA1 + bo + B_BYTES);
        // hh
        mma_bf16(acc[0][0], ah0, bh0); mma_bf16(acc[0][1], ah0, bh0 + 2);
        mma_bf16(acc[0][2], ah0, bh1); mma_bf16(acc[0][3], ah0, bh1 + 2);
        mma_bf16(acc[1][0], ah1, bh0); mma_bf16(acc[1][1], ah1, bh0 + 2);
        mma_bf16(acc[1][2], ah1, bh1); mma_bf16(acc[1][3], ah1, bh1 + 2);
        // hl
        mma_bf16(acc[0][0], ah0, bl0); mma_bf16(acc[0][1], ah0, bl0 + 2);
        mma_bf16(acc[0][2], ah0, bl1); mma_bf16(acc[0][3], ah0, bl1 + 2);
        mma_bf16(acc[1][0], ah1, bl0); mma_bf16(acc[1][1], ah1, bl0 + 2);
        mma_bf16(acc[1][2], ah1, bl1); mma_bf16(acc[1][3], ah1, bl1 + 2);
        // lh (A-lo loaded late: keeps peak register pressure low)
        uint32_t al0[4], al1[4];
        ldsm_x4(al0, aHi0 + (uint32_t)A_BYTES + 32u * s);
        ldsm_x4(al1, aHi1 + (uint32_t)A_BYTES + 32u * s);
        mma_bf16(acc[0][0], al0, bh0); mma_bf16(acc[0][1], al0, bh0 + 2);
        mma_bf16(acc[0][2], al0, bh1); mma_bf16(acc[0][3], al0, bh1 + 2);
        mma_bf16(acc[1][0], al1, bh0); mma_bf16(acc[1][1], al1, bh0 + 2);
        mma_bf16(acc[1][2], al1, bh1); mma_bf16(acc[1][3], al1, bh1 + 2);
    }

    // ---- Epilogue: SMEM transpose -> coalesced float4 row stores ----
    __syncthreads();
    float* smT = (float*)smem;   // [32][264] = 33792 B
    const int mi = lane >> 2;
    const int nf = (lane & 3) * 2;
#pragma unroll
    for (int m = 0; m < 2; m++) {
        int cw = 32 * w + 16 * m + mi;
#pragma unroll
        for (int t = 0; t < 4; t++) {
            smT[(8 * t + nf) * 264 + cw]         = acc[m][t][0];
            smT[(8 * t + nf + 1) * 264 + cw]     = acc[m][t][1];
            smT[(8 * t + nf) * 264 + cw + 8]     = acc[m][t][2];
            smT[(8 * t + nf + 1) * 264 + cw + 8] = acc[m][t][3];
        }
    }
    __syncthreads();
    const int n = tid >> 3, cq = tid & 7;        // 8 threads per row
    const float* srow = smT + n * 264 + 32 * cq;
    if (MODE == 0) {
        float4* orow = (float4*)(g_resid + (size_t)(r0 + n) * LDIM + c0 + 32 * cq);
#pragma unroll
        for (int i = 0; i < 8; i++)
            orow[i] = make_float4(srow[4 * i], srow[4 * i + 1],
                                  srow[4 * i + 2], srow[4 * i + 3]);
    } else {
        const float sv = __ldg(step);
        float4* orow = (float4*)(out + (size_t)(r0 + n) * LDIM + c0 + 32 * cq);
#pragma unroll
        for (int i = 0; i < 8; i++) {
            float a0 = sv * srow[4 * i + 0];
            float a1 = sv * srow[4 * i + 1];
            float a2 = sv * srow[4 * i + 2];
            float a3 = sv * srow[4 * i + 3];
            orow[i] = make_float4(
                copysignf(TITER * fmaxf(fabsf(a0) - LAMBDA, 0.0f), a0),
                copysignf(TITER * fmaxf(fabsf(a1) - LAMBDA, 0.0f), a1),
                copysignf(TITER * fmaxf(fabsf(a2) - LAMBDA, 0.0f), a2),
                copysignf(TITER * fmaxf(fabsf(a3) - LAMBDA, 0.0f), a3));
        }
    }
}

extern "C" void kernel_launch(void* const* d_in, const int* in_sizes, int n_in,
                              void* d_out, int out_size)
{
    const float* y = nullptr;
    const float* h = nullptr;
    const float* s = nullptr;
    for (int i = 0; i < n_in; i++) {
        if (in_sizes[i] == BDIM * LDIM)      y = (const float*)d_in[i];
        else if (in_sizes[i] == KW)          h = (const float*)d_in[i];
        else if (in_sizes[i] == 1)           s = (const float*)d_in[i];
    }
    cudaFuncSetAttribute(conv_mma_kernel<0>,
                         cudaFuncAttributeMaxDynamicSharedMemorySize, SM_TOTAL);
    cudaFuncSetAttribute(conv_mma_kernel<1>,
                         cudaFuncAttributeMaxDynamicSharedMemorySize, SM_TOTAL);
    dim3 grid(LDIM / COLS, BDIM / ROWS);   // (16, 128)
    conv_mma_kernel<0><<<grid, NTH, SM_TOTAL>>>(y, h, s, (float*)d_out);
    conv_mma_kernel<1><<<grid, NTH, SM_TOTAL>>>(y, h, s, (float*)d_out);
}